// round 14
// baseline (speedup 1.0000x reference)
#include <cuda_runtime.h>
#include <cuda_fp16.h>
#include <cstdint>

#define Bn 128
#define Nn 256
#define Dn 512
#define Hn 1024
#define Ln 3

// ---------------------------------------------------------------------------
// Scratch planes (single fp16 plane each; 16B-aligned)
// ---------------------------------------------------------------------------
__device__ __align__(256) __half g_adjh[Nn * Nn];
__device__ __align__(256) __half g_xh [(size_t)Bn * Nn * Dn];
__device__ __align__(256) __half g_nbh[(size_t)Bn * Nn * Dn];
__device__ __align__(256) __half g_hh [(size_t)Bn * Nn * Hn];
__device__ __align__(256) __half g_w1h[(size_t)Ln * Hn * Dn];
__device__ __align__(256) __half g_w2h[(size_t)Ln * Dn * Hn];
__device__ __align__(256) float  g_x  [(size_t)Bn * Nn * Dn];

// ---------------------------------------------------------------------------
// PTX helpers
// ---------------------------------------------------------------------------
__device__ __forceinline__ uint32_t smem_u32(const void* p) {
    uint32_t a;
    asm("{ .reg .u64 t; cvta.to.shared.u64 t, %1; cvt.u32.u64 %0, t; }"
        : "=r"(a) : "l"(p));
    return a;
}
__device__ __forceinline__ void cp16(uint32_t s, const void* g) {
    asm volatile("cp.async.cg.shared.global [%0], [%1], 16;" :: "r"(s), "l"(g));
}
__device__ __forceinline__ void cp_commit() {
    asm volatile("cp.async.commit_group;" ::: "memory");
}
template<int N>
__device__ __forceinline__ void cp_wait() {
    asm volatile("cp.async.wait_group %0;" :: "n"(N) : "memory");
}
__device__ __forceinline__ void ldsm_x4(uint32_t (&r)[4], uint32_t addr) {
    asm volatile("ldmatrix.sync.aligned.m8n8.x4.shared.b16 {%0,%1,%2,%3}, [%4];"
        : "=r"(r[0]), "=r"(r[1]), "=r"(r[2]), "=r"(r[3]) : "r"(addr));
}
__device__ __forceinline__ void ldsm_x4_t(uint32_t (&r)[4], uint32_t addr) {
    asm volatile("ldmatrix.sync.aligned.m8n8.x4.trans.shared.b16 {%0,%1,%2,%3}, [%4];"
        : "=r"(r[0]), "=r"(r[1]), "=r"(r[2]), "=r"(r[3]) : "r"(addr));
}
__device__ __forceinline__ void mma16816(float (&d)[4], const uint32_t (&a)[4],
                                         uint32_t b0, uint32_t b1) {
    asm volatile(
        "mma.sync.aligned.m16n8k16.row.col.f32.f16.f16.f32 "
        "{%0,%1,%2,%3}, {%4,%5,%6,%7}, {%8,%9}, {%0,%1,%2,%3};"
        : "+f"(d[0]), "+f"(d[1]), "+f"(d[2]), "+f"(d[3])
        : "r"(a[0]), "r"(a[1]), "r"(a[2]), "r"(a[3]), "r"(b0), "r"(b1));
}

// ---------------------------------------------------------------------------
// Row softmax over adjacency [N,N]: fp32 output + fp16 plane
// ---------------------------------------------------------------------------
__global__ void softmax_rows(const float* __restrict__ adj,
                             float* __restrict__ out_adj,
                             __half* __restrict__ hi)
{
    int row = blockIdx.x;
    int t   = threadIdx.x;
    float v = adj[row * Nn + t];

    __shared__ float red[8];
    float m = v;
    #pragma unroll
    for (int o = 16; o > 0; o >>= 1)
        m = fmaxf(m, __shfl_xor_sync(0xffffffffu, m, o));
    if ((t & 31) == 0) red[t >> 5] = m;
    __syncthreads();
    m = red[0];
    #pragma unroll
    for (int i = 1; i < 8; i++) m = fmaxf(m, red[i]);
    __syncthreads();

    float e = expf(v - m);
    float s = e;
    #pragma unroll
    for (int o = 16; o > 0; o >>= 1)
        s += __shfl_xor_sync(0xffffffffu, s, o);
    if ((t & 31) == 0) red[t >> 5] = s;
    __syncthreads();
    s = red[0];
    #pragma unroll
    for (int i = 1; i < 8; i++) s += red[i];

    float o = e / s;
    out_adj[row * Nn + t] = o;
    hi[row * Nn + t] = __float2half_rn(o);
}

// ---------------------------------------------------------------------------
// One merged fp32 -> fp16 conversion over W1 | W2 | x0 (range dispatch)
// ---------------------------------------------------------------------------
#define W_N4  (Ln * Hn * Dn / 4)
#define X_N4  ((int)((size_t)Bn * Nn * Dn / 4))
#define ALL_N4 (2 * W_N4 + X_N4)

__global__ void cvt_all(const float* __restrict__ W1, const float* __restrict__ W2,
                        const float* __restrict__ X0,
                        __half* __restrict__ w1h, __half* __restrict__ w2h,
                        __half* __restrict__ xh)
{
    int idx = blockIdx.x * blockDim.x + threadIdx.x;
    if (idx >= ALL_N4) return;
    const float* in;
    __half* hi;
    int off;
    if (idx < W_N4)            { in = W1; hi = w1h; off = 0; }
    else if (idx < 2 * W_N4)   { in = W2; hi = w2h; off = W_N4; }
    else                       { in = X0; hi = xh;  off = 2 * W_N4; }
    int j = idx - off;
    float4 v = ((const float4*)in)[j];
    __half h0 = __float2half_rn(v.x), h1 = __float2half_rn(v.y);
    __half h2 = __float2half_rn(v.z), h3 = __float2half_rn(v.w);
    ((uint2*)hi)[j] = make_uint2(
        (uint32_t)__half_as_ushort(h0) | ((uint32_t)__half_as_ushort(h1) << 16),
        (uint32_t)__half_as_ushort(h2) | ((uint32_t)__half_as_ushort(h3) << 16));
}

// ---------------------------------------------------------------------------
// Plain fp16 GEMM (fp32 accumulate): C = act(A @ op(B) + bias) (+resid)
//   A: fp16 [M,K] row-major
//   B NT: fp16 [Ncol,K] row-major (weights); B T: fp16 [K,Ncol] (x, batched z)
// CTA tile 256x128xKc64, 256 threads = 8 warps (4x2), warp tile 64x64.
// 2-stage cp.async, R12 pipeline (issue-then-wait<1>, two barriers/chunk).
// ---------------------------------------------------------------------------
#define PITCH    72      // halves; 144B rows
#define PITCH_BT 136     // halves; 272B rows (B-T tile, 64 x 128)
#define SLOT_A   36864   // bytes: 256*72*2
#define SLOT_B   18432   // bytes: 128*72*2 (B-T: 64*136*2=17408 fits)
#define STAGE_B  (SLOT_A + SLOT_B)
#define DSMEM_B  (2 * STAGE_B)

template<bool TRANSB, bool HASBIAS, bool RELU, bool RESID, bool OUTF32, bool OUTHALF>
__global__ void __launch_bounds__(256, 1)
mma_gemm(const __half* __restrict__ Ah, const __half* __restrict__ Bh,
         const float* __restrict__ bias, const float* __restrict__ resid,
         float* __restrict__ Cf, __half* __restrict__ Ch,
         int Ncol, int K)
{
    extern __shared__ __align__(16) char dsm[];
    __shared__ float sbias[128];

    const int tid  = threadIdx.x;
    const int lane = tid & 31;
    const int wid  = tid >> 5;
    const int mwarp = (wid >> 1) * 64;   // 0,64,128,192
    const int nwarp = (wid & 1) * 64;    // 0 or 64
    const int bm = blockIdx.y * 256;
    const int bn = blockIdx.x * 128;
    const int z  = blockIdx.z;

    const size_t arow0 = (size_t)bm;
    const __half* Bhp = Bh;
    size_t out_row0;
    if (TRANSB) {
        Bhp = Bh + (size_t)z * Nn * Dn;
        out_row0 = (size_t)z * Nn + bm;
    } else {
        out_row0 = (size_t)bm;
    }

    if (HASBIAS && tid < 128) sbias[tid] = bias[bn + tid];

    float acc[4][8][4];
    #pragma unroll
    for (int mi = 0; mi < 4; mi++)
        #pragma unroll
        for (int ni = 0; ni < 8; ni++)
            #pragma unroll
            for (int e = 0; e < 4; e++) acc[mi][ni][e] = 0.f;

    const uint32_t dsm_u = smem_u32(dsm);

    // per-thread ldmatrix base offsets (byte, within a stage)
    const int q = lane >> 3, li = lane & 7;
    const uint32_t aLds = (uint32_t)(((mwarp + (q & 1) * 8 + li) * PITCH
                                     + (q >> 1) * 8) << 1);
    uint32_t bLds;
    if (TRANSB)
        bLds = (uint32_t)((((q & 1) * 8 + li) * PITCH_BT
                          + nwarp + (q >> 1) * 8) << 1);
    else
        bLds = (uint32_t)(((nwarp + (q >> 1) * 8 + li) * PITCH
                          + (q & 1) * 8) << 1);

    // issue cp.async loads for one 64-k chunk into stage s
    auto issue = [&](int k0, int s) {
        const uint32_t sa = dsm_u + (uint32_t)s * STAGE_B;
        const uint32_t sb = sa + SLOT_A;
        // A: 256 rows x 64 halves = 2048 16B lines / 256 thr = 8 iters
        #pragma unroll
        for (int i = 0; i < 8; i++) {
            int f = tid + i * 256;
            int r = f >> 3, c = (f & 7) << 3;      // r: 0..255, c: 0..56
            uint32_t so = (uint32_t)((r * PITCH + c) << 1);
            cp16(sa + so, Ah + (arow0 + r) * (size_t)K + k0 + c);
        }
        // B: 1024 16B lines / 256 thr = 4 iters
        #pragma unroll
        for (int i = 0; i < 4; i++) {
            int f = tid + i * 256;
            if (TRANSB) {
                int rb = f >> 4, cb = (f & 15) << 3;   // rb: 0..63, cb: 0..120
                uint32_t sob = (uint32_t)((rb * PITCH_BT + cb) << 1);
                cp16(sb + sob, Bhp + (size_t)(k0 + rb) * Ncol + bn + cb);
            } else {
                int r = f >> 3, c = (f & 7) << 3;      // r: 0..127, c: 0..56
                uint32_t so = (uint32_t)((r * PITCH + c) << 1);
                cp16(sb + so, Bhp + (size_t)(bn + r) * K + k0 + c);
            }
        }
        cp_commit();
    };

    // fragment double buffers
    uint32_t af[2][4][4];
    uint32_t bh[2][4][4];

    const int nchunks = K >> 6;
    issue(0, 0);

    for (int ch = 0; ch < nchunks; ch++) {
        if (ch + 1 < nchunks) {
            issue((ch + 1) << 6, (ch + 1) & 1);
            cp_wait<1>();
        } else {
            cp_wait<0>();
        }
        __syncthreads();

        const uint32_t stg = dsm_u + (uint32_t)(ch & 1) * STAGE_B;
        const uint32_t sa  = stg + aLds;
        const uint32_t sb  = stg + SLOT_A + bLds;

        // load fragments for ks=0 into buffer 0
        #pragma unroll
        for (int nj = 0; nj < 4; nj++) {
            if (TRANSB) ldsm_x4_t(bh[0][nj], sb + (uint32_t)((nj * 16) << 1));
            else        ldsm_x4  (bh[0][nj], sb + (uint32_t)((nj * 16 * PITCH) << 1));
        }
        #pragma unroll
        for (int mi = 0; mi < 4; mi++)
            ldsm_x4(af[0][mi], sa + (uint32_t)((mi * 16 * PITCH) << 1));

        #pragma unroll
        for (int ks = 0; ks < 4; ks++) {
            const int cur = ks & 1;
            const int nxt = cur ^ 1;
            if (ks < 3) {
                #pragma unroll
                for (int nj = 0; nj < 4; nj++) {
                    if (TRANSB)
                        ldsm_x4_t(bh[nxt][nj],
                                  sb + (uint32_t)(((ks + 1) * 16 * PITCH_BT + nj * 16) << 1));
                    else
                        ldsm_x4(bh[nxt][nj],
                                sb + (uint32_t)((nj * 16 * PITCH + (ks + 1) * 16) << 1));
                }
                #pragma unroll
                for (int mi = 0; mi < 4; mi++)
                    ldsm_x4(af[nxt][mi],
                            sa + (uint32_t)((mi * 16 * PITCH + (ks + 1) * 16) << 1));
            }
            #pragma unroll
            for (int mi = 0; mi < 4; mi++)
                #pragma unroll
                for (int ni = 0; ni < 8; ni++) {
                    int nj = ni >> 1, p = (ni & 1) * 2;
                    mma16816(acc[mi][ni], af[cur][mi], bh[cur][nj][p], bh[cur][nj][p + 1]);
                }
        }
        __syncthreads();
    }

    // ---- epilogue ----
    const int rql = lane >> 2;
    const int cql = (lane & 3) << 1;
    #pragma unroll
    for (int mi = 0; mi < 4; mi++) {
        #pragma unroll
        for (int ni = 0; ni < 8; ni++) {
            int coln = nwarp + ni * 8 + cql;
            float b0 = 0.f, b1 = 0.f;
            if (HASBIAS) { b0 = sbias[coln]; b1 = sbias[coln + 1]; }
            #pragma unroll
            for (int half = 0; half < 2; half++) {
                size_t row = out_row0 + mwarp + mi * 16 + rql + half * 8;
                float v0 = acc[mi][ni][half * 2 + 0] + b0;
                float v1 = acc[mi][ni][half * 2 + 1] + b1;
                if (RELU) { v0 = fmaxf(v0, 0.f); v1 = fmaxf(v1, 0.f); }
                size_t goff = row * (size_t)Ncol + bn + coln;
                if (RESID) {
                    float2 r = *(const float2*)(resid + goff);
                    v0 += r.x; v1 += r.y;
                }
                if (OUTF32) *(float2*)(Cf + goff) = make_float2(v0, v1);
                if (OUTHALF) {
                    __half h0 = __float2half_rn(v0), h1 = __float2half_rn(v1);
                    *(uint32_t*)(Ch + goff) =
                        (uint32_t)__half_as_ushort(h0) |
                        ((uint32_t)__half_as_ushort(h1) << 16);
                }
            }
        }
    }
}

// ---------------------------------------------------------------------------
__global__ void pool_mean(const float* __restrict__ x, float* __restrict__ pooled)
{
    int idx = blockIdx.x * blockDim.x + threadIdx.x;
    int b = idx / Dn;
    int d = idx - b * Dn;
    const float* p = x + (size_t)b * Nn * Dn + d;
    float s = 0.f;
    #pragma unroll 8
    for (int n = 0; n < Nn; n++) s += p[(size_t)n * Dn];
    pooled[idx] = s * (1.f / Nn);
}

// ---------------------------------------------------------------------------
extern "C" void kernel_launch(void* const* d_in, const int* in_sizes, int n_in,
                              void* d_out, int out_size)
{
    const float* x0  = (const float*)d_in[0];
    const float* adj = (const float*)d_in[1];
    const float* W1  = (const float*)d_in[2];
    const float* b1  = (const float*)d_in[3];
    const float* W2  = (const float*)d_in[4];
    const float* b2  = (const float*)d_in[5];

    float* out      = (float*)d_out;
    float* out_x    = out;
    float* out_pool = out + (size_t)Bn * Nn * Dn;
    float* out_adj  = out_pool + (size_t)Bn * Dn;

    __half *adjh, *xh, *nbh, *hh, *w1h, *w2h;
    float* gx;
    cudaGetSymbolAddress((void**)&adjh, g_adjh);
    cudaGetSymbolAddress((void**)&xh,   g_xh);
    cudaGetSymbolAddress((void**)&nbh,  g_nbh);
    cudaGetSymbolAddress((void**)&hh,   g_hh);
    cudaGetSymbolAddress((void**)&w1h,  g_w1h);
    cudaGetSymbolAddress((void**)&w2h,  g_w2h);
    cudaGetSymbolAddress((void**)&gx,   g_x);

    cudaFuncSetAttribute(mma_gemm<true,  false, false, false, false, true>,
        cudaFuncAttributeMaxDynamicSharedMemorySize, DSMEM_B);
    cudaFuncSetAttribute(mma_gemm<false, true,  true,  false, false, true>,
        cudaFuncAttributeMaxDynamicSharedMemorySize, DSMEM_B);
    cudaFuncSetAttribute(mma_gemm<false, true,  false, true,  true,  true>,
        cudaFuncAttributeMaxDynamicSharedMemorySize, DSMEM_B);
    cudaFuncSetAttribute(mma_gemm<false, true,  false, true,  true,  false>,
        cudaFuncAttributeMaxDynamicSharedMemorySize, DSMEM_B);

    softmax_rows<<<Nn, Nn>>>(adj, out_adj, adjh);
    cvt_all<<<(ALL_N4 + 255) / 256, 256>>>(W1, W2, x0, w1h, w2h, xh);

    const float* xin_f = x0;
    for (int i = 0; i < Ln; i++) {
        float* xout = (i == Ln - 1) ? out_x : gx;
        bool last = (i == Ln - 1);

        // neighbor = adj_norm @ x  (M=256 per batch -> grid y = 1)
        mma_gemm<true, false, false, false, false, true>
            <<<dim3(Dn / 128, Nn / 256, Bn), 256, DSMEM_B>>>(
            adjh, xh, nullptr, nullptr, nullptr, nbh, Dn, Nn);

        // h = relu(nb @ W1^T + b1) -> h fp16
        mma_gemm<false, true, true, false, false, true>
            <<<dim3(Hn / 128, (Bn * Nn) / 256, 1), 256, DSMEM_B>>>(
            nbh, w1h + (size_t)i * Hn * Dn,
            b1 + (size_t)i * Hn, nullptr, nullptr, hh, Hn, Dn);

        // x = x + h @ W2^T + b2
        if (!last)
            mma_gemm<false, true, false, true, true, true>
                <<<dim3(Dn / 128, (Bn * Nn) / 256, 1), 256, DSMEM_B>>>(
                hh, w2h + (size_t)i * Dn * Hn,
                b2 + (size_t)i * Dn, xin_f, xout, xh, Dn, Hn);
        else
            mma_gemm<false, true, false, true, true, false>
                <<<dim3(Dn / 128, (Bn * Nn) / 256, 1), 256, DSMEM_B>>>(
                hh, w2h + (size_t)i * Dn * Hn,
                b2 + (size_t)i * Dn, xin_f, xout, nullptr, Dn, Hn);

        xin_f = xout;
    }

    pool_mean<<<(Bn * Dn) / 256, 256>>>(out_x, out_pool);
}

// round 15
// speedup vs baseline: 1.2308x; 1.2308x over previous
#include <cuda_runtime.h>
#include <cuda_fp16.h>
#include <cstdint>

#define Bn 128
#define Nn 256
#define Dn 512
#define Hn 1024
#define Ln 3

// ---------------------------------------------------------------------------
// Scratch planes (single fp16 plane each; 16B-aligned)
// ---------------------------------------------------------------------------
__device__ __align__(256) __half g_adjh[Nn * Nn];
__device__ __align__(256) __half g_xh [(size_t)Bn * Nn * Dn];
__device__ __align__(256) __half g_nbh[(size_t)Bn * Nn * Dn];
__device__ __align__(256) __half g_hh [(size_t)Bn * Nn * Hn];
__device__ __align__(256) __half g_w1h[(size_t)Ln * Hn * Dn];
__device__ __align__(256) __half g_w2h[(size_t)Ln * Dn * Hn];
__device__ __align__(256) float  g_x  [(size_t)Bn * Nn * Dn];
__device__ __align__(256) float  g_pp [(Bn * Nn / 128) * Dn];   // colsum partials

// ---------------------------------------------------------------------------
// PTX helpers
// ---------------------------------------------------------------------------
__device__ __forceinline__ uint32_t smem_u32(const void* p) {
    uint32_t a;
    asm("{ .reg .u64 t; cvta.to.shared.u64 t, %1; cvt.u32.u64 %0, t; }"
        : "=r"(a) : "l"(p));
    return a;
}
__device__ __forceinline__ void cp16(uint32_t s, const void* g) {
    asm volatile("cp.async.cg.shared.global [%0], [%1], 16;" :: "r"(s), "l"(g));
}
__device__ __forceinline__ void cp_commit() {
    asm volatile("cp.async.commit_group;" ::: "memory");
}
template<int N>
__device__ __forceinline__ void cp_wait() {
    asm volatile("cp.async.wait_group %0;" :: "n"(N) : "memory");
}
__device__ __forceinline__ void ldsm_x4(uint32_t (&r)[4], uint32_t addr) {
    asm volatile("ldmatrix.sync.aligned.m8n8.x4.shared.b16 {%0,%1,%2,%3}, [%4];"
        : "=r"(r[0]), "=r"(r[1]), "=r"(r[2]), "=r"(r[3]) : "r"(addr));
}
__device__ __forceinline__ void ldsm_x4_t(uint32_t (&r)[4], uint32_t addr) {
    asm volatile("ldmatrix.sync.aligned.m8n8.x4.trans.shared.b16 {%0,%1,%2,%3}, [%4];"
        : "=r"(r[0]), "=r"(r[1]), "=r"(r[2]), "=r"(r[3]) : "r"(addr));
}
__device__ __forceinline__ void mma16816(float (&d)[4], const uint32_t (&a)[4],
                                         uint32_t b0, uint32_t b1) {
    asm volatile(
        "mma.sync.aligned.m16n8k16.row.col.f32.f16.f16.f32 "
        "{%0,%1,%2,%3}, {%4,%5,%6,%7}, {%8,%9}, {%0,%1,%2,%3};"
        : "+f"(d[0]), "+f"(d[1]), "+f"(d[2]), "+f"(d[3])
        : "r"(a[0]), "r"(a[1]), "r"(a[2]), "r"(a[3]), "r"(b0), "r"(b1));
}

// ---------------------------------------------------------------------------
// Merged prep kernel: blocks [0, Nn) do softmax rows; the rest convert
// W1 | W2 | x0 fp32 -> fp16 (range dispatch).
// ---------------------------------------------------------------------------
#define W_N4  (Ln * Hn * Dn / 4)
#define X_N4  ((int)((size_t)Bn * Nn * Dn / 4))
#define ALL_N4 (2 * W_N4 + X_N4)
#define PREP_BLOCKS (Nn + (ALL_N4 + 255) / 256)

__global__ void prep_all(const float* __restrict__ adj,
                         float* __restrict__ out_adj,
                         __half* __restrict__ adjh,
                         const float* __restrict__ W1, const float* __restrict__ W2,
                         const float* __restrict__ X0,
                         __half* __restrict__ w1h, __half* __restrict__ w2h,
                         __half* __restrict__ xh)
{
    if (blockIdx.x < Nn) {
        // ---- softmax over one adjacency row ----
        int row = blockIdx.x;
        int t   = threadIdx.x;
        float v = adj[row * Nn + t];

        __shared__ float red[8];
        float m = v;
        #pragma unroll
        for (int o = 16; o > 0; o >>= 1)
            m = fmaxf(m, __shfl_xor_sync(0xffffffffu, m, o));
        if ((t & 31) == 0) red[t >> 5] = m;
        __syncthreads();
        m = red[0];
        #pragma unroll
        for (int i = 1; i < 8; i++) m = fmaxf(m, red[i]);
        __syncthreads();

        float e = expf(v - m);
        float s = e;
        #pragma unroll
        for (int o = 16; o > 0; o >>= 1)
            s += __shfl_xor_sync(0xffffffffu, s, o);
        if ((t & 31) == 0) red[t >> 5] = s;
        __syncthreads();
        s = red[0];
        #pragma unroll
        for (int i = 1; i < 8; i++) s += red[i];

        float o = e / s;
        out_adj[row * Nn + t] = o;
        adjh[row * Nn + t] = __float2half_rn(o);
        return;
    }

    int idx = (blockIdx.x - Nn) * blockDim.x + threadIdx.x;
    if (idx >= ALL_N4) return;
    const float* in;
    __half* hi;
    int off;
    if (idx < W_N4)          { in = W1; hi = w1h; off = 0; }
    else if (idx < 2 * W_N4) { in = W2; hi = w2h; off = W_N4; }
    else                     { in = X0; hi = xh;  off = 2 * W_N4; }
    int j = idx - off;
    float4 v = ((const float4*)in)[j];
    __half h0 = __float2half_rn(v.x), h1 = __float2half_rn(v.y);
    __half h2 = __float2half_rn(v.z), h3 = __float2half_rn(v.w);
    ((uint2*)hi)[j] = make_uint2(
        (uint32_t)__half_as_ushort(h0) | ((uint32_t)__half_as_ushort(h1) << 16),
        (uint32_t)__half_as_ushort(h2) | ((uint32_t)__half_as_ushort(h3) << 16));
}

// ---------------------------------------------------------------------------
// Plain fp16 GEMM (fp32 accumulate): C = act(A @ op(B) + bias) (+resid)
//   A: fp16 [M,K] row-major
//   B NT: fp16 [Ncol,K] row-major (weights); B T: fp16 [K,Ncol] (x, batched z)
// CTA tile 128x128xKc64, 128 threads (2x2 warps, warp tile 64x64).
// 2-stage cp.async (R12 pipeline). POOLOUT: emit per-CTA column sums to pp.
// ---------------------------------------------------------------------------
#define PITCH    72      // halves; 144B rows
#define PITCH_BT 136     // halves; 272B rows (B-T tile, 64 x 128)
#define SLOT_B   18432   // bytes per operand slot
#define STAGE_B  (2 * SLOT_B)
#define DSMEM_B  (2 * STAGE_B)

template<bool TRANSB, bool HASBIAS, bool RELU, bool RESID, bool OUTF32, bool OUTHALF, bool POOLOUT>
__global__ void __launch_bounds__(128, 2)
mma_gemm(const __half* __restrict__ Ah, const __half* __restrict__ Bh,
         const float* __restrict__ bias, const float* __restrict__ resid,
         float* __restrict__ Cf, __half* __restrict__ Ch,
         float* __restrict__ pp,
         int Ncol, int K)
{
    extern __shared__ __align__(16) char dsm[];
    __shared__ float sbias[128];
    __shared__ float spool[128];   // POOLOUT: colsums from upper-m warps

    const int tid  = threadIdx.x;
    const int lane = tid & 31;
    const int wid  = tid >> 5;
    const int mwarp = (wid >> 1) * 64;
    const int nwarp = (wid & 1) * 64;
    const int bm = blockIdx.y * 128;
    const int bn = blockIdx.x * 128;
    const int z  = blockIdx.z;

    const size_t arow0 = (size_t)bm;
    const __half* Bhp = Bh;
    size_t out_row0;
    if (TRANSB) {
        Bhp = Bh + (size_t)z * Nn * Dn;
        out_row0 = (size_t)z * Nn + bm;
    } else {
        out_row0 = (size_t)bm;
    }

    if (HASBIAS && tid < 128) sbias[tid] = bias[bn + tid];

    float acc[4][8][4];
    #pragma unroll
    for (int mi = 0; mi < 4; mi++)
        #pragma unroll
        for (int ni = 0; ni < 8; ni++)
            #pragma unroll
            for (int e = 0; e < 4; e++) acc[mi][ni][e] = 0.f;

    const uint32_t dsm_u = smem_u32(dsm);

    const int q = lane >> 3, li = lane & 7;
    const uint32_t aLds = (uint32_t)(((mwarp + (q & 1) * 8 + li) * PITCH
                                     + (q >> 1) * 8) << 1);
    uint32_t bLds;
    if (TRANSB)
        bLds = (uint32_t)((((q & 1) * 8 + li) * PITCH_BT
                          + nwarp + (q >> 1) * 8) << 1);
    else
        bLds = (uint32_t)(((nwarp + (q >> 1) * 8 + li) * PITCH
                          + (q & 1) * 8) << 1);

    auto issue = [&](int k0, int s) {
        const uint32_t sa = dsm_u + (uint32_t)s * STAGE_B;
        const uint32_t sb = sa + SLOT_B;
        #pragma unroll
        for (int i = 0; i < 8; i++) {
            int f = tid + i * 128;
            int r = f >> 3, c = (f & 7) << 3;
            uint32_t so = (uint32_t)((r * PITCH + c) << 1);
            cp16(sa + so, Ah + (arow0 + r) * (size_t)K + k0 + c);
            if (TRANSB) {
                int rb = f >> 4, cb = (f & 15) << 3;
                uint32_t sob = (uint32_t)((rb * PITCH_BT + cb) << 1);
                cp16(sb + sob, Bhp + (size_t)(k0 + rb) * Ncol + bn + cb);
            } else {
                cp16(sb + so, Bhp + (size_t)(bn + r) * K + k0 + c);
            }
        }
        cp_commit();
    };

    uint32_t af[2][4][4];
    uint32_t bh[2][4][4];

    const int nchunks = K >> 6;
    issue(0, 0);

    for (int ch = 0; ch < nchunks; ch++) {
        if (ch + 1 < nchunks) {
            issue((ch + 1) << 6, (ch + 1) & 1);
            cp_wait<1>();
        } else {
            cp_wait<0>();
        }
        __syncthreads();

        const uint32_t stg = dsm_u + (uint32_t)(ch & 1) * STAGE_B;
        const uint32_t sa  = stg + aLds;
        const uint32_t sb  = stg + SLOT_B + bLds;

        #pragma unroll
        for (int nj = 0; nj < 4; nj++) {
            if (TRANSB) ldsm_x4_t(bh[0][nj], sb + (uint32_t)((nj * 16) << 1));
            else        ldsm_x4  (bh[0][nj], sb + (uint32_t)((nj * 16 * PITCH) << 1));
        }
        #pragma unroll
        for (int mi = 0; mi < 4; mi++)
            ldsm_x4(af[0][mi], sa + (uint32_t)((mi * 16 * PITCH) << 1));

        #pragma unroll
        for (int ks = 0; ks < 4; ks++) {
            const int cur = ks & 1;
            const int nxt = cur ^ 1;
            if (ks < 3) {
                #pragma unroll
                for (int nj = 0; nj < 4; nj++) {
                    if (TRANSB)
                        ldsm_x4_t(bh[nxt][nj],
                                  sb + (uint32_t)(((ks + 1) * 16 * PITCH_BT + nj * 16) << 1));
                    else
                        ldsm_x4(bh[nxt][nj],
                                sb + (uint32_t)((nj * 16 * PITCH + (ks + 1) * 16) << 1));
                }
                #pragma unroll
                for (int mi = 0; mi < 4; mi++)
                    ldsm_x4(af[nxt][mi],
                            sa + (uint32_t)((mi * 16 * PITCH + (ks + 1) * 16) << 1));
            }
            #pragma unroll
            for (int mi = 0; mi < 4; mi++)
                #pragma unroll
                for (int ni = 0; ni < 8; ni++) {
                    int nj = ni >> 1, p = (ni & 1) * 2;
                    mma16816(acc[mi][ni], af[cur][mi], bh[cur][nj][p], bh[cur][nj][p + 1]);
                }
        }
        __syncthreads();
    }

    // ---- epilogue ----
    const int rql = lane >> 2;
    const int cql = (lane & 3) << 1;
    float csum[8][2];   // POOLOUT: per-thread column partial over its rows
    if (POOLOUT) {
        #pragma unroll
        for (int ni = 0; ni < 8; ni++) { csum[ni][0] = 0.f; csum[ni][1] = 0.f; }
    }

    #pragma unroll
    for (int mi = 0; mi < 4; mi++) {
        #pragma unroll
        for (int ni = 0; ni < 8; ni++) {
            int coln = nwarp + ni * 8 + cql;
            float b0 = 0.f, b1 = 0.f;
            if (HASBIAS) { b0 = sbias[coln]; b1 = sbias[coln + 1]; }
            #pragma unroll
            for (int half = 0; half < 2; half++) {
                size_t row = out_row0 + mwarp + mi * 16 + rql + half * 8;
                float v0 = acc[mi][ni][half * 2 + 0] + b0;
                float v1 = acc[mi][ni][half * 2 + 1] + b1;
                if (RELU) { v0 = fmaxf(v0, 0.f); v1 = fmaxf(v1, 0.f); }
                size_t goff = row * (size_t)Ncol + bn + coln;
                if (RESID) {
                    float2 r = *(const float2*)(resid + goff);
                    v0 += r.x; v1 += r.y;
                }
                if (OUTF32) *(float2*)(Cf + goff) = make_float2(v0, v1);
                if (OUTHALF) {
                    __half h0 = __float2half_rn(v0), h1 = __float2half_rn(v1);
                    *(uint32_t*)(Ch + goff) =
                        (uint32_t)__half_as_ushort(h0) |
                        ((uint32_t)__half_as_ushort(h1) << 16);
                }
                if (POOLOUT) { csum[ni][0] += v0; csum[ni][1] += v1; }
            }
        }
    }

    if (POOLOUT) {
        // reduce across the 8 rql lane-groups (stride 4,8,16)
        #pragma unroll
        for (int ni = 0; ni < 8; ni++)
            #pragma unroll
            for (int e = 0; e < 2; e++) {
                float s = csum[ni][e];
                #pragma unroll
                for (int o = 16; o >= 4; o >>= 1)
                    s += __shfl_xor_sync(0xffffffffu, s, o);
                csum[ni][e] = s;   // valid on lanes 0..3
            }
        // upper-m warps (wid 2,3) publish their 64-col sums
        if (wid >= 2 && lane < 4) {
            #pragma unroll
            for (int ni = 0; ni < 8; ni++) {
                spool[nwarp + ni * 8 + cql]     = csum[ni][0];
                spool[nwarp + ni * 8 + cql + 1] = csum[ni][1];
            }
        }
        __syncthreads();
        // lower-m warps (wid 0,1) combine and store partials
        if (wid < 2 && lane < 4) {
            int rowblock = (int)(out_row0 >> 7);   // 128-row block id
            #pragma unroll
            for (int ni = 0; ni < 8; ni++) {
                int c0 = nwarp + ni * 8 + cql;
                pp[(size_t)rowblock * Ncol + bn + c0]     = csum[ni][0] + spool[c0];
                pp[(size_t)rowblock * Ncol + bn + c0 + 1] = csum[ni][1] + spool[c0 + 1];
            }
        }
    }
}

// ---------------------------------------------------------------------------
// pooled[b][d] = (pp[2b][d] + pp[2b+1][d]) / Nn
// ---------------------------------------------------------------------------
__global__ void pool_final(const float* __restrict__ pp, float* __restrict__ pooled)
{
    int idx = blockIdx.x * blockDim.x + threadIdx.x;   // b*Dn + d
    int b = idx / Dn;
    int d = idx - b * Dn;
    pooled[idx] = (pp[(size_t)(2 * b) * Dn + d] + pp[(size_t)(2 * b + 1) * Dn + d])
                  * (1.f / Nn);
}

// ---------------------------------------------------------------------------
extern "C" void kernel_launch(void* const* d_in, const int* in_sizes, int n_in,
                              void* d_out, int out_size)
{
    const float* x0  = (const float*)d_in[0];
    const float* adj = (const float*)d_in[1];
    const float* W1  = (const float*)d_in[2];
    const float* b1  = (const float*)d_in[3];
    const float* W2  = (const float*)d_in[4];
    const float* b2  = (const float*)d_in[5];

    float* out      = (float*)d_out;
    float* out_x    = out;
    float* out_pool = out + (size_t)Bn * Nn * Dn;
    float* out_adj  = out_pool + (size_t)Bn * Dn;

    __half *adjh, *xh, *nbh, *hh, *w1h, *w2h;
    float *gx, *gpp;
    cudaGetSymbolAddress((void**)&adjh, g_adjh);
    cudaGetSymbolAddress((void**)&xh,   g_xh);
    cudaGetSymbolAddress((void**)&nbh,  g_nbh);
    cudaGetSymbolAddress((void**)&hh,   g_hh);
    cudaGetSymbolAddress((void**)&w1h,  g_w1h);
    cudaGetSymbolAddress((void**)&w2h,  g_w2h);
    cudaGetSymbolAddress((void**)&gx,   g_x);
    cudaGetSymbolAddress((void**)&gpp,  g_pp);

    cudaFuncSetAttribute(mma_gemm<true,  false, false, false, false, true,  false>,
        cudaFuncAttributeMaxDynamicSharedMemorySize, DSMEM_B);
    cudaFuncSetAttribute(mma_gemm<false, true,  true,  false, false, true,  false>,
        cudaFuncAttributeMaxDynamicSharedMemorySize, DSMEM_B);
    cudaFuncSetAttribute(mma_gemm<false, true,  false, true,  true,  true,  false>,
        cudaFuncAttributeMaxDynamicSharedMemorySize, DSMEM_B);
    cudaFuncSetAttribute(mma_gemm<false, true,  false, true,  true,  false, true>,
        cudaFuncAttributeMaxDynamicSharedMemorySize, DSMEM_B);

    prep_all<<<PREP_BLOCKS, 256>>>(adj, out_adj, adjh, W1, W2, x0, w1h, w2h, xh);

    const float* xin_f = x0;
    for (int i = 0; i < Ln; i++) {
        float* xout = (i == Ln - 1) ? out_x : gx;
        bool last = (i == Ln - 1);

        // neighbor = adj_norm @ x  -> nb fp16
        mma_gemm<true, false, false, false, false, true, false>
            <<<dim3(Dn / 128, Nn / 128, Bn), 128, DSMEM_B>>>(
            adjh, xh, nullptr, nullptr, nullptr, nbh, nullptr, Dn, Nn);

        // h = relu(nb @ W1^T + b1) -> h fp16
        mma_gemm<false, true, true, false, false, true, false>
            <<<dim3(Hn / 128, (Bn * Nn) / 128, 1), 128, DSMEM_B>>>(
            nbh, w1h + (size_t)i * Hn * Dn,
            b1 + (size_t)i * Hn, nullptr, nullptr, hh, nullptr, Hn, Dn);

        // x = x + h @ W2^T + b2
        if (!last)
            mma_gemm<false, true, false, true, true, true, false>
                <<<dim3(Dn / 128, (Bn * Nn) / 128, 1), 128, DSMEM_B>>>(
                hh, w2h + (size_t)i * Dn * Hn,
                b2 + (size_t)i * Dn, xin_f, xout, xh, nullptr, Dn, Hn);
        else
            mma_gemm<false, true, false, true, true, false, true>
                <<<dim3(Dn / 128, (Bn * Nn) / 128, 1), 128, DSMEM_B>>>(
                hh, w2h + (size_t)i * Dn * Hn,
                b2 + (size_t)i * Dn, xin_f, xout, nullptr, gpp, Dn, Hn);

        xin_f = xout;
    }

    pool_final<<<(Bn * Dn) / 256, 256>>>(gpp, out_pool);
}

// round 16
// speedup vs baseline: 1.2655x; 1.0282x over previous
#include <cuda_runtime.h>
#include <cuda_fp16.h>
#include <cstdint>

#define Bn 128
#define Nn 256
#define Dn 512
#define Hn 1024
#define Ln 3

// ---------------------------------------------------------------------------
// Scratch planes (single fp16 plane each; 16B-aligned)
// ---------------------------------------------------------------------------
__device__ __align__(256) __half g_adjh[Nn * Nn];
__device__ __align__(256) __half g_xh [(size_t)Bn * Nn * Dn];   // x carrier (in-place)
__device__ __align__(256) __half g_nbh[(size_t)Bn * Nn * Dn];
__device__ __align__(256) __half g_hh [(size_t)Bn * Nn * Hn];
__device__ __align__(256) __half g_w1h[(size_t)Ln * Hn * Dn];
__device__ __align__(256) __half g_w2h[(size_t)Ln * Dn * Hn];
__device__ __align__(256) float  g_pp [(Bn * Nn / 128) * Dn];   // colsum partials

// ---------------------------------------------------------------------------
// PTX helpers
// ---------------------------------------------------------------------------
__device__ __forceinline__ uint32_t smem_u32(const void* p) {
    uint32_t a;
    asm("{ .reg .u64 t; cvta.to.shared.u64 t, %1; cvt.u32.u64 %0, t; }"
        : "=r"(a) : "l"(p));
    return a;
}
__device__ __forceinline__ void cp16(uint32_t s, const void* g) {
    asm volatile("cp.async.cg.shared.global [%0], [%1], 16;" :: "r"(s), "l"(g));
}
__device__ __forceinline__ void cp_commit() {
    asm volatile("cp.async.commit_group;" ::: "memory");
}
template<int N>
__device__ __forceinline__ void cp_wait() {
    asm volatile("cp.async.wait_group %0;" :: "n"(N) : "memory");
}
__device__ __forceinline__ void ldsm_x4(uint32_t (&r)[4], uint32_t addr) {
    asm volatile("ldmatrix.sync.aligned.m8n8.x4.shared.b16 {%0,%1,%2,%3}, [%4];"
        : "=r"(r[0]), "=r"(r[1]), "=r"(r[2]), "=r"(r[3]) : "r"(addr));
}
__device__ __forceinline__ void ldsm_x4_t(uint32_t (&r)[4], uint32_t addr) {
    asm volatile("ldmatrix.sync.aligned.m8n8.x4.trans.shared.b16 {%0,%1,%2,%3}, [%4];"
        : "=r"(r[0]), "=r"(r[1]), "=r"(r[2]), "=r"(r[3]) : "r"(addr));
}
__device__ __forceinline__ void mma16816(float (&d)[4], const uint32_t (&a)[4],
                                         uint32_t b0, uint32_t b1) {
    asm volatile(
        "mma.sync.aligned.m16n8k16.row.col.f32.f16.f16.f32 "
        "{%0,%1,%2,%3}, {%4,%5,%6,%7}, {%8,%9}, {%0,%1,%2,%3};"
        : "+f"(d[0]), "+f"(d[1]), "+f"(d[2]), "+f"(d[3])
        : "r"(a[0]), "r"(a[1]), "r"(a[2]), "r"(a[3]), "r"(b0), "r"(b1));
}

// ---------------------------------------------------------------------------
// Merged prep kernel: blocks [0, Nn) do softmax rows; the rest convert
// W1 | W2 | x0 fp32 -> fp16 (range dispatch).
// ---------------------------------------------------------------------------
#define W_N4  (Ln * Hn * Dn / 4)
#define X_N4  ((int)((size_t)Bn * Nn * Dn / 4))
#define ALL_N4 (2 * W_N4 + X_N4)
#define PREP_BLOCKS (Nn + (ALL_N4 + 255) / 256)

__global__ void prep_all(const float* __restrict__ adj,
                         float* __restrict__ out_adj,
                         __half* __restrict__ adjh,
                         const float* __restrict__ W1, const float* __restrict__ W2,
                         const float* __restrict__ X0,
                         __half* __restrict__ w1h, __half* __restrict__ w2h,
                         __half* __restrict__ xh)
{
    if (blockIdx.x < Nn) {
        int row = blockIdx.x;
        int t   = threadIdx.x;
        float v = adj[row * Nn + t];

        __shared__ float red[8];
        float m = v;
        #pragma unroll
        for (int o = 16; o > 0; o >>= 1)
            m = fmaxf(m, __shfl_xor_sync(0xffffffffu, m, o));
        if ((t & 31) == 0) red[t >> 5] = m;
        __syncthreads();
        m = red[0];
        #pragma unroll
        for (int i = 1; i < 8; i++) m = fmaxf(m, red[i]);
        __syncthreads();

        float e = expf(v - m);
        float s = e;
        #pragma unroll
        for (int o = 16; o > 0; o >>= 1)
            s += __shfl_xor_sync(0xffffffffu, s, o);
        if ((t & 31) == 0) red[t >> 5] = s;
        __syncthreads();
        s = red[0];
        #pragma unroll
        for (int i = 1; i < 8; i++) s += red[i];

        float o = e / s;
        out_adj[row * Nn + t] = o;
        adjh[row * Nn + t] = __float2half_rn(o);
        return;
    }

    int idx = (blockIdx.x - Nn) * blockDim.x + threadIdx.x;
    if (idx >= ALL_N4) return;
    const float* in;
    __half* hi;
    int off;
    if (idx < W_N4)          { in = W1; hi = w1h; off = 0; }
    else if (idx < 2 * W_N4) { in = W2; hi = w2h; off = W_N4; }
    else                     { in = X0; hi = xh;  off = 2 * W_N4; }
    int j = idx - off;
    float4 v = ((const float4*)in)[j];
    __half h0 = __float2half_rn(v.x), h1 = __float2half_rn(v.y);
    __half h2 = __float2half_rn(v.z), h3 = __float2half_rn(v.w);
    ((uint2*)hi)[j] = make_uint2(
        (uint32_t)__half_as_ushort(h0) | ((uint32_t)__half_as_ushort(h1) << 16),
        (uint32_t)__half_as_ushort(h2) | ((uint32_t)__half_as_ushort(h3) << 16));
}

// ---------------------------------------------------------------------------
// Plain fp16 GEMM (fp32 accumulate): C = act(A @ op(B) + bias) (+resid fp16)
//   A: fp16 [M,K] row-major
//   B NT: fp16 [Ncol,K] row-major (weights); B T: fp16 [K,Ncol] (x, batched z)
// CTA tile 128x128xKc64, 128 threads (2x2 warps, warp tile 64x64).
// 2-stage cp.async (R12 pipeline). POOLOUT: emit per-CTA column sums to pp.
// RESID: fp16 residual read (from xh); in-place with OUTHALF to the same buffer.
// ---------------------------------------------------------------------------
#define PITCH    72      // halves; 144B rows
#define PITCH_BT 136     // halves; 272B rows (B-T tile, 64 x 128)
#define SLOT_B   18432   // bytes per operand slot
#define STAGE_B  (2 * SLOT_B)
#define DSMEM_B  (2 * STAGE_B)

template<bool TRANSB, bool HASBIAS, bool RELU, bool RESID, bool OUTF32, bool OUTHALF, bool POOLOUT>
__global__ void __launch_bounds__(128, 2)
mma_gemm(const __half* __restrict__ Ah, const __half* __restrict__ Bh,
         const float* __restrict__ bias, const __half* __restrict__ resid,
         float* __restrict__ Cf, __half* __restrict__ Ch,
         float* __restrict__ pp,
         int Ncol, int K)
{
    extern __shared__ __align__(16) char dsm[];
    __shared__ float sbias[128];
    __shared__ float spool[128];

    const int tid  = threadIdx.x;
    const int lane = tid & 31;
    const int wid  = tid >> 5;
    const int mwarp = (wid >> 1) * 64;
    const int nwarp = (wid & 1) * 64;
    const int bm = blockIdx.y * 128;
    const int bn = blockIdx.x * 128;
    const int z  = blockIdx.z;

    const size_t arow0 = (size_t)bm;
    const __half* Bhp = Bh;
    size_t out_row0;
    if (TRANSB) {
        Bhp = Bh + (size_t)z * Nn * Dn;
        out_row0 = (size_t)z * Nn + bm;
    } else {
        out_row0 = (size_t)bm;
    }

    if (HASBIAS && tid < 128) sbias[tid] = bias[bn + tid];

    float acc[4][8][4];
    #pragma unroll
    for (int mi = 0; mi < 4; mi++)
        #pragma unroll
        for (int ni = 0; ni < 8; ni++)
            #pragma unroll
            for (int e = 0; e < 4; e++) acc[mi][ni][e] = 0.f;

    const uint32_t dsm_u = smem_u32(dsm);

    const int q = lane >> 3, li = lane & 7;
    const uint32_t aLds = (uint32_t)(((mwarp + (q & 1) * 8 + li) * PITCH
                                     + (q >> 1) * 8) << 1);
    uint32_t bLds;
    if (TRANSB)
        bLds = (uint32_t)((((q & 1) * 8 + li) * PITCH_BT
                          + nwarp + (q >> 1) * 8) << 1);
    else
        bLds = (uint32_t)(((nwarp + (q >> 1) * 8 + li) * PITCH
                          + (q & 1) * 8) << 1);

    auto issue = [&](int k0, int s) {
        const uint32_t sa = dsm_u + (uint32_t)s * STAGE_B;
        const uint32_t sb = sa + SLOT_B;
        #pragma unroll
        for (int i = 0; i < 8; i++) {
            int f = tid + i * 128;
            int r = f >> 3, c = (f & 7) << 3;
            uint32_t so = (uint32_t)((r * PITCH + c) << 1);
            cp16(sa + so, Ah + (arow0 + r) * (size_t)K + k0 + c);
            if (TRANSB) {
                int rb = f >> 4, cb = (f & 15) << 3;
                uint32_t sob = (uint32_t)((rb * PITCH_BT + cb) << 1);
                cp16(sb + sob, Bhp + (size_t)(k0 + rb) * Ncol + bn + cb);
            } else {
                cp16(sb + so, Bhp + (size_t)(bn + r) * K + k0 + c);
            }
        }
        cp_commit();
    };

    uint32_t af[2][4][4];
    uint32_t bh[2][4][4];

    const int nchunks = K >> 6;
    issue(0, 0);

    for (int ch = 0; ch < nchunks; ch++) {
        if (ch + 1 < nchunks) {
            issue((ch + 1) << 6, (ch + 1) & 1);
            cp_wait<1>();
        } else {
            cp_wait<0>();
        }
        __syncthreads();

        const uint32_t stg = dsm_u + (uint32_t)(ch & 1) * STAGE_B;
        const uint32_t sa  = stg + aLds;
        const uint32_t sb  = stg + SLOT_B + bLds;

        #pragma unroll
        for (int nj = 0; nj < 4; nj++) {
            if (TRANSB) ldsm_x4_t(bh[0][nj], sb + (uint32_t)((nj * 16) << 1));
            else        ldsm_x4  (bh[0][nj], sb + (uint32_t)((nj * 16 * PITCH) << 1));
        }
        #pragma unroll
        for (int mi = 0; mi < 4; mi++)
            ldsm_x4(af[0][mi], sa + (uint32_t)((mi * 16 * PITCH) << 1));

        #pragma unroll
        for (int ks = 0; ks < 4; ks++) {
            const int cur = ks & 1;
            const int nxt = cur ^ 1;
            if (ks < 3) {
                #pragma unroll
                for (int nj = 0; nj < 4; nj++) {
                    if (TRANSB)
                        ldsm_x4_t(bh[nxt][nj],
                                  sb + (uint32_t)(((ks + 1) * 16 * PITCH_BT + nj * 16) << 1));
                    else
                        ldsm_x4(bh[nxt][nj],
                                sb + (uint32_t)((nj * 16 * PITCH + (ks + 1) * 16) << 1));
                }
                #pragma unroll
                for (int mi = 0; mi < 4; mi++)
                    ldsm_x4(af[nxt][mi],
                            sa + (uint32_t)((mi * 16 * PITCH + (ks + 1) * 16) << 1));
            }
            #pragma unroll
            for (int mi = 0; mi < 4; mi++)
                #pragma unroll
                for (int ni = 0; ni < 8; ni++) {
                    int nj = ni >> 1, p = (ni & 1) * 2;
                    mma16816(acc[mi][ni], af[cur][mi], bh[cur][nj][p], bh[cur][nj][p + 1]);
                }
        }
        __syncthreads();
    }

    // ---- epilogue ----
    const int rql = lane >> 2;
    const int cql = (lane & 3) << 1;
    float csum[8][2];
    if (POOLOUT) {
        #pragma unroll
        for (int ni = 0; ni < 8; ni++) { csum[ni][0] = 0.f; csum[ni][1] = 0.f; }
    }

    #pragma unroll
    for (int mi = 0; mi < 4; mi++) {
        #pragma unroll
        for (int ni = 0; ni < 8; ni++) {
            int coln = nwarp + ni * 8 + cql;
            float b0 = 0.f, b1 = 0.f;
            if (HASBIAS) { b0 = sbias[coln]; b1 = sbias[coln + 1]; }
            #pragma unroll
            for (int half = 0; half < 2; half++) {
                size_t row = out_row0 + mwarp + mi * 16 + rql + half * 8;
                float v0 = acc[mi][ni][half * 2 + 0] + b0;
                float v1 = acc[mi][ni][half * 2 + 1] + b1;
                if (RELU) { v0 = fmaxf(v0, 0.f); v1 = fmaxf(v1, 0.f); }
                size_t goff = row * (size_t)Ncol + bn + coln;
                if (RESID) {
                    uint32_t rp = *(const uint32_t*)(resid + goff);
                    __half rl = __ushort_as_half((uint16_t)(rp & 0xFFFF));
                    __half rh = __ushort_as_half((uint16_t)(rp >> 16));
                    v0 += __half2float(rl);
                    v1 += __half2float(rh);
                }
                if (OUTF32) *(float2*)(Cf + goff) = make_float2(v0, v1);
                if (OUTHALF) {
                    __half h0 = __float2half_rn(v0), h1 = __float2half_rn(v1);
                    *(uint32_t*)(Ch + goff) =
                        (uint32_t)__half_as_ushort(h0) |
                        ((uint32_t)__half_as_ushort(h1) << 16);
                }
                if (POOLOUT) { csum[ni][0] += v0; csum[ni][1] += v1; }
            }
        }
    }

    if (POOLOUT) {
        #pragma unroll
        for (int ni = 0; ni < 8; ni++)
            #pragma unroll
            for (int e = 0; e < 2; e++) {
                float s = csum[ni][e];
                #pragma unroll
                for (int o = 16; o >= 4; o >>= 1)
                    s += __shfl_xor_sync(0xffffffffu, s, o);
                csum[ni][e] = s;
            }
        if (wid >= 2 && lane < 4) {
            #pragma unroll
            for (int ni = 0; ni < 8; ni++) {
                spool[nwarp + ni * 8 + cql]     = csum[ni][0];
                spool[nwarp + ni * 8 + cql + 1] = csum[ni][1];
            }
        }
        __syncthreads();
        if (wid < 2 && lane < 4) {
            int rowblock = (int)(out_row0 >> 7);
            #pragma unroll
            for (int ni = 0; ni < 8; ni++) {
                int c0 = nwarp + ni * 8 + cql;
                pp[(size_t)rowblock * Ncol + bn + c0]     = csum[ni][0] + spool[c0];
                pp[(size_t)rowblock * Ncol + bn + c0 + 1] = csum[ni][1] + spool[c0 + 1];
            }
        }
    }
}

// ---------------------------------------------------------------------------
// pooled[b][d] = (pp[2b][d] + pp[2b+1][d]) / Nn
// ---------------------------------------------------------------------------
__global__ void pool_final(const float* __restrict__ pp, float* __restrict__ pooled)
{
    int idx = blockIdx.x * blockDim.x + threadIdx.x;
    int b = idx / Dn;
    int d = idx - b * Dn;
    pooled[idx] = (pp[(size_t)(2 * b) * Dn + d] + pp[(size_t)(2 * b + 1) * Dn + d])
                  * (1.f / Nn);
}

// ---------------------------------------------------------------------------
extern "C" void kernel_launch(void* const* d_in, const int* in_sizes, int n_in,
                              void* d_out, int out_size)
{
    const float* x0  = (const float*)d_in[0];
    const float* adj = (const float*)d_in[1];
    const float* W1  = (const float*)d_in[2];
    const float* b1  = (const float*)d_in[3];
    const float* W2  = (const float*)d_in[4];
    const float* b2  = (const float*)d_in[5];

    float* out      = (float*)d_out;
    float* out_x    = out;
    float* out_pool = out + (size_t)Bn * Nn * Dn;
    float* out_adj  = out_pool + (size_t)Bn * Dn;

    __half *adjh, *xh, *nbh, *hh, *w1h, *w2h;
    float *gpp;
    cudaGetSymbolAddress((void**)&adjh, g_adjh);
    cudaGetSymbolAddress((void**)&xh,   g_xh);
    cudaGetSymbolAddress((void**)&nbh,  g_nbh);
    cudaGetSymbolAddress((void**)&hh,   g_hh);
    cudaGetSymbolAddress((void**)&w1h,  g_w1h);
    cudaGetSymbolAddress((void**)&w2h,  g_w2h);
    cudaGetSymbolAddress((void**)&gpp,  g_pp);

    cudaFuncSetAttribute(mma_gemm<true,  false, false, false, false, true,  false>,
        cudaFuncAttributeMaxDynamicSharedMemorySize, DSMEM_B);
    cudaFuncSetAttribute(mma_gemm<false, true,  true,  false, false, true,  false>,
        cudaFuncAttributeMaxDynamicSharedMemorySize, DSMEM_B);
    cudaFuncSetAttribute(mma_gemm<false, true,  false, true,  false, true,  false>,
        cudaFuncAttributeMaxDynamicSharedMemorySize, DSMEM_B);
    cudaFuncSetAttribute(mma_gemm<false, true,  false, true,  true,  false, true>,
        cudaFuncAttributeMaxDynamicSharedMemorySize, DSMEM_B);

    prep_all<<<PREP_BLOCKS, 256>>>(adj, out_adj, adjh, W1, W2, x0, w1h, w2h, xh);

    for (int i = 0; i < Ln; i++) {
        bool last = (i == Ln - 1);

        // neighbor = adj_norm @ x  -> nb fp16
        mma_gemm<true, false, false, false, false, true, false>
            <<<dim3(Dn / 128, Nn / 128, Bn), 128, DSMEM_B>>>(
            adjh, xh, nullptr, nullptr, nullptr, nbh, nullptr, Dn, Nn);

        // h = relu(nb @ W1^T + b1) -> h fp16
        mma_gemm<false, true, true, false, false, true, false>
            <<<dim3(Hn / 128, (Bn * Nn) / 128, 1), 128, DSMEM_B>>>(
            nbh, w1h + (size_t)i * Hn * Dn,
            b1 + (size_t)i * Hn, nullptr, nullptr, hh, nullptr, Hn, Dn);

        // x = x + h @ W2^T + b2   (resid read fp16 from xh; in-place update)
        if (!last)
            mma_gemm<false, true, false, true, false, true, false>
                <<<dim3(Dn / 128, (Bn * Nn) / 128, 1), 128, DSMEM_B>>>(
                hh, w2h + (size_t)i * Dn * Hn,
                b2 + (size_t)i * Dn, xh, nullptr, xh, nullptr, Dn, Hn);
        else
            mma_gemm<false, true, false, true, true, false, true>
                <<<dim3(Dn / 128, (Bn * Nn) / 128, 1), 128, DSMEM_B>>>(
                hh, w2h + (size_t)i * Dn * Hn,
                b2 + (size_t)i * Dn, xh, out_x, nullptr, gpp, Dn, Hn);
    }

    pool_final<<<(Bn * Dn) / 256, 256>>>(gpp, out_pool);
}